// round 1
// baseline (speedup 1.0000x reference)
#include <cuda_runtime.h>
#include <cuda_bf16.h>
#include <cstdint>

#define N_ROWS   32768
#define HDIM     1024
#define N_MOTIF  128
#define N_CLASS  16
#define NPC      8
#define K2       32
#define EPS_C    1e-4f
#define TAU_C    0.99f

// ---------------- device scratch (static allocations are allowed) ----------------
__device__ float g_distT[(size_t)N_MOTIF * N_ROWS];   // 16 MB, distance transposed [motif][row]
__device__ int   g_y[N_ROWS];
__device__ float g_loss_partial[256];

// ---------------- helpers ----------------
__device__ __forceinline__ float rcp_newton(float x) {
    // bit-trick initial guess + 3 Newton iterations: rel err ~1e-8, no MUFU
    float y = __uint_as_float(0x7EF311C3u - __float_as_uint(x));
    y = y * fmaf(-x, y, 2.f);
    y = y * fmaf(-x, y, 2.f);
    y = y * fmaf(-x, y, 2.f);
    return y;
}

#define NEG_INF __int_as_float(0xff800000)

// ---------------- y conversion (handles int64 or int32 storage) ----------------
__global__ void k_yconv(const int* __restrict__ yraw) {
    __shared__ int is64;
    int t = threadIdx.x;
    if (t == 0) {
        int f = 1;
        for (int i = 0; i < 32; i++)
            if (yraw[2 * i + 1] != 0) { f = 0; break; }
        is64 = f;
    }
    __syncthreads();
    if (is64) {
        for (int i = t; i < N_ROWS; i += 256) g_y[i] = yraw[2 * i];
    } else {
        for (int i = t; i < N_ROWS; i += 256) g_y[i] = yraw[i];
    }
}

// ---------------- fused GEMM + distance + loss-row-stats kernel ----------------
// block: 256 threads (8 warps, 4x2), tile 128 rows x 128 motifs, K chunks of 32
#define KC 32
#define KP (KC + 2)   // padded smem stride (34 bf16 = 68B, 17 words: conflict-light)

struct __align__(16) SmemU {
    union {
        struct {
            __nv_bfloat16 zA[128][KP];
            __nv_bfloat16 mB[128][KP];
        } ab;
        float xp[64][129];   // epilogue staging, half-tile, padded
    } u;
};

__global__ __launch_bounds__(256, 1)
void k_gemm(const float* __restrict__ z, const float* __restrict__ M) {
    __shared__ SmemU sm;
    __shared__ float zn_s[128], mn_s[128], loss_s[128];

    const int t    = threadIdx.x;
    const int lane = t & 31;
    const int w    = t >> 5;
    const int wm   = w >> 1;   // 0..3
    const int wn   = w & 1;    // 0..1
    const int r0   = blockIdx.x * 128;

    // loader mapping: 2 threads per row, 16 contiguous floats each
    const int lrow = t >> 1;
    const int part = t & 1;
    const float* zg = z + (size_t)(r0 + lrow) * HDIM + part * 16;
    const float* mg = M + (size_t)lrow * HDIM + part * 16;

    float acc[2][8][4];
#pragma unroll
    for (int a = 0; a < 2; a++)
#pragma unroll
        for (int b = 0; b < 8; b++)
#pragma unroll
            for (int c = 0; c < 4; c++) acc[a][b][c] = 0.f;

    float zsq = 0.f, msq = 0.f;
    float4 zr[4], mr[4];
#pragma unroll
    for (int j = 0; j < 4; j++) {
        zr[j] = *(const float4*)(zg + 4 * j);
        mr[j] = *(const float4*)(mg + 4 * j);
    }

    const int kq = 2 * (lane & 3);
    const int rA = lane >> 2;

    for (int ch = 0; ch < 32; ch++) {
        // stage registers -> smem (convert to bf16), accumulate sumsq
#pragma unroll
        for (int j = 0; j < 4; j++) {
            float4 v = zr[j];
            zsq = fmaf(v.x, v.x, zsq); zsq = fmaf(v.y, v.y, zsq);
            zsq = fmaf(v.z, v.z, zsq); zsq = fmaf(v.w, v.w, zsq);
            *(__nv_bfloat162*)&sm.u.ab.zA[lrow][part * 16 + 4 * j]     = __floats2bfloat162_rn(v.x, v.y);
            *(__nv_bfloat162*)&sm.u.ab.zA[lrow][part * 16 + 4 * j + 2] = __floats2bfloat162_rn(v.z, v.w);
            float4 m = mr[j];
            msq = fmaf(m.x, m.x, msq); msq = fmaf(m.y, m.y, msq);
            msq = fmaf(m.z, m.z, msq); msq = fmaf(m.w, m.w, msq);
            *(__nv_bfloat162*)&sm.u.ab.mB[lrow][part * 16 + 4 * j]     = __floats2bfloat162_rn(m.x, m.y);
            *(__nv_bfloat162*)&sm.u.ab.mB[lrow][part * 16 + 4 * j + 2] = __floats2bfloat162_rn(m.z, m.w);
        }
        __syncthreads();

        // prefetch next chunk (overlaps with mma below)
        if (ch < 31) {
            zg += KC; mg += KC;
#pragma unroll
            for (int j = 0; j < 4; j++) {
                zr[j] = *(const float4*)(zg + 4 * j);
                mr[j] = *(const float4*)(mg + 4 * j);
            }
        }

        // mma over this chunk: 2 k-steps of 16
#pragma unroll
        for (int ks = 0; ks < KC; ks += 16) {
            uint32_t af[2][4];
#pragma unroll
            for (int mt = 0; mt < 2; mt++) {
                int rb = wm * 32 + mt * 16 + rA;
                af[mt][0] = *(const uint32_t*)&sm.u.ab.zA[rb][ks + kq];
                af[mt][1] = *(const uint32_t*)&sm.u.ab.zA[rb + 8][ks + kq];
                af[mt][2] = *(const uint32_t*)&sm.u.ab.zA[rb][ks + kq + 8];
                af[mt][3] = *(const uint32_t*)&sm.u.ab.zA[rb + 8][ks + kq + 8];
            }
            uint32_t bf[8][2];
#pragma unroll
            for (int nt = 0; nt < 8; nt++) {
                int nb = wn * 64 + nt * 8 + rA;
                bf[nt][0] = *(const uint32_t*)&sm.u.ab.mB[nb][ks + kq];
                bf[nt][1] = *(const uint32_t*)&sm.u.ab.mB[nb][ks + kq + 8];
            }
#pragma unroll
            for (int mt = 0; mt < 2; mt++)
#pragma unroll
                for (int nt = 0; nt < 8; nt++) {
                    asm volatile(
                        "mma.sync.aligned.m16n8k16.row.col.f32.bf16.bf16.f32 "
                        "{%0,%1,%2,%3},{%4,%5,%6,%7},{%8,%9},{%0,%1,%2,%3};"
                        : "+f"(acc[mt][nt][0]), "+f"(acc[mt][nt][1]),
                          "+f"(acc[mt][nt][2]), "+f"(acc[mt][nt][3])
                        : "r"(af[mt][0]), "r"(af[mt][1]), "r"(af[mt][2]), "r"(af[mt][3]),
                          "r"(bf[nt][0]), "r"(bf[nt][1]));
                }
        }
        if (ch < 31) __syncthreads();
    }

    // row norms: combine the two half-row partials (adjacent lanes)
    {
        float zo = __shfl_xor_sync(0xffffffffu, zsq, 1);
        float mo = __shfl_xor_sync(0xffffffffu, msq, 1);
        if (part == 0) { zn_s[lrow] = zsq + zo; mn_s[lrow] = msq + mo; }
    }

    // epilogue: two halves of 64 rows through smem staging
    for (int half = 0; half < 2; half++) {
        __syncthreads();
        if ((wm >> 1) == half) {
            int mrel = wm - half * 2;   // 0 or 1
#pragma unroll
            for (int mt = 0; mt < 2; mt++)
#pragma unroll
                for (int nt = 0; nt < 8; nt++)
#pragma unroll
                    for (int r = 0; r < 4; r++) {
                        int row = mrel * 32 + mt * 16 + rA + 8 * (r >> 1);
                        int col = wn * 64 + nt * 8 + 2 * (lane & 3) + (r & 1);
                        sm.u.xp[row][col] = acc[mt][nt][r];
                    }
        }
        __syncthreads();

        // loss row stats: 4 threads per row, 32 cols each
        {
            int rloc = t >> 2, q = t & 3;
            int grow = r0 + half * 64 + rloc;
            int ycls = g_y[grow];
            float znv = zn_s[half * 64 + rloc];
            float pmax = NEG_INF, nsum = 0.f;
#pragma unroll 8
            for (int c = q * 32; c < q * 32 + 32; c++) {
                float d  = fmaf(-2.f, sm.u.xp[rloc][c], znv + mn_s[c]);
                float x  = d + EPS_C;
                float dl = (1.f - EPS_C) * rcp_newton(x);
                float rr = 1.f + dl;
                float r2 = rr * rr;
                float s  = r2 * r2 * rr;           // ((d+1)/(d+eps))^5 == exp(sim/T)
                if ((c >> 3) == ycls) pmax = fmaxf(pmax, s);
                else nsum += s;
            }
            nsum += __shfl_xor_sync(0xffffffffu, nsum, 1);
            nsum += __shfl_xor_sync(0xffffffffu, nsum, 2);
            pmax = fmaxf(pmax, __shfl_xor_sync(0xffffffffu, pmax, 1));
            pmax = fmaxf(pmax, __shfl_xor_sync(0xffffffffu, pmax, 2));
            if (q == 0) loss_s[half * 64 + rloc] = log1pf(nsum / pmax);
        }

        // transposed distance write: coalesced columns
        {
            int cc  = t >> 6;       // 0..3
            int rr2 = t & 63;
            float znv2 = zn_s[half * 64 + rr2];
#pragma unroll
            for (int c0 = 0; c0 < 128; c0 += 4) {
                int c = c0 + cc;
                float d = fmaf(-2.f, sm.u.xp[rr2][c], znv2 + mn_s[c]);
                g_distT[(size_t)c * N_ROWS + r0 + half * 64 + rr2] = d;
            }
        }
    }

    __syncthreads();
    // deterministic block loss reduce
    for (int s = 64; s > 0; s >>= 1) {
        if (t < s) loss_s[t] += loss_s[t + s];
        __syncthreads();
    }
    if (t == 0) g_loss_partial[blockIdx.x] = loss_s[0];
}

// ---------------- top-k (K2 largest distances per motif among class rows) + motif update ----------------
#define CAP 6080   // expected class size ~2048; huge safety margin; 48.6KB smem

__global__ __launch_bounds__(256)
void k_topk(const float* __restrict__ z, const float* __restrict__ M,
            float* __restrict__ out, int moff, int writeM) {
    __shared__ float sv[CAP];
    __shared__ int   si[CAP];
    __shared__ int   cnt;
    __shared__ float wv[8];
    __shared__ int   wi[8], wp[8];
    __shared__ int   selIdx[K2];

    const int t   = threadIdx.x;
    const int j   = blockIdx.x;
    const int cls = j >> 3;

    if (t == 0) cnt = 0;
    __syncthreads();

    const float* dcol = g_distT + (size_t)j * N_ROWS;
    for (int i = t; i < N_ROWS; i += 256) {
        if (g_y[i] == cls) {
            int p = atomicAdd(&cnt, 1);
            if (p < CAP) { sv[p] = dcol[i]; si[p] = i; }
        }
    }
    __syncthreads();
    const int n = min(cnt, CAP);

    for (int k = 0; k < K2; k++) {
        float bv = NEG_INF; int bi = 0x7fffffff; int bp = -1;
        for (int p = t; p < n; p += 256) {
            float v = sv[p]; int ii = si[p];
            if (v > bv || (v == bv && ii < bi)) { bv = v; bi = ii; bp = p; }
        }
#pragma unroll
        for (int o = 16; o > 0; o >>= 1) {
            float ov = __shfl_xor_sync(0xffffffffu, bv, o);
            int   oi = __shfl_xor_sync(0xffffffffu, bi, o);
            int   op = __shfl_xor_sync(0xffffffffu, bp, o);
            if (ov > bv || (ov == bv && oi < bi)) { bv = ov; bi = oi; bp = op; }
        }
        if ((t & 31) == 0) { wv[t >> 5] = bv; wi[t >> 5] = bi; wp[t >> 5] = bp; }
        __syncthreads();
        if (t == 0) {
            bv = wv[0]; bi = wi[0]; bp = wp[0];
            for (int q = 1; q < 8; q++)
                if (wv[q] > bv || (wv[q] == bv && wi[q] < bi)) { bv = wv[q]; bi = wi[q]; bp = wp[q]; }
            selIdx[k] = bi;
            if (bp >= 0) sv[bp] = NEG_INF;
        }
        __syncthreads();
    }

    // gather-mean of 32 selected z rows; blend with M
    float a0 = 0.f, a1 = 0.f, a2 = 0.f, a3 = 0.f;
    for (int k = 0; k < K2; k++) {
        const float* zr = z + (size_t)selIdx[k] * HDIM;
        a0 += zr[t]; a1 += zr[t + 256]; a2 += zr[t + 512]; a3 += zr[t + 768];
    }
    if (writeM) {
        const float* mr = M + (size_t)j * HDIM;
        float* o = out + moff + (size_t)j * HDIM;
        const float invk = 1.f / (float)K2;
        const float om = 1.f - TAU_C;
        o[t]       = TAU_C * mr[t]       + om * (a0 * invk);
        o[t + 256] = TAU_C * mr[t + 256] + om * (a1 * invk);
        o[t + 512] = TAU_C * mr[t + 512] + om * (a2 * invk);
        o[t + 768] = TAU_C * mr[t + 768] + om * (a3 * invk);
    }
}

// ---------------- final loss reduction ----------------
__global__ void k_lossfin(float* __restrict__ out, int idx) {
    __shared__ float s[256];
    int t = threadIdx.x;
    s[t] = g_loss_partial[t];
    __syncthreads();
    for (int d = 128; d > 0; d >>= 1) {
        if (t < d) s[t] += s[t + d];
        __syncthreads();
    }
    if (t == 0) out[idx] = s[0] * (1.f / (float)N_ROWS);
}

// ---------------- entry ----------------
extern "C" void kernel_launch(void* const* d_in, const int* in_sizes, int n_in,
                              void* d_out, int out_size) {
    const float* z = (const float*)d_in[0];
    const float* M = (const float*)d_in[1];
    const int*   y = (const int*)d_in[2];
    float* out = (float*)d_out;

    int moff, writeM, writeLoss;
    if (out_size >= N_MOTIF * HDIM + 1)      { moff = 1; writeM = 1; writeLoss = 1; }
    else if (out_size >= N_MOTIF * HDIM)     { moff = 0; writeM = 1; writeLoss = 0; }
    else                                     { moff = 0; writeM = 0; writeLoss = 1; }

    k_yconv<<<1, 256>>>(y);
    k_gemm<<<N_ROWS / 128, 256>>>(z, M);
    k_topk<<<N_MOTIF, 256>>>(z, M, out, moff, writeM);
    if (writeLoss) k_lossfin<<<1, 256>>>(out, 0);
}